// round 1
// baseline (speedup 1.0000x reference)
#include <cuda_runtime.h>

// Problem constants (fixed shapes per reference)
#define NVOX 32768      // 32*32*32
#define CDIM 128
#define SCALE 0.17677669529663689f   // 1/sqrt(32)

// Scratch (allocation-free: device globals)
__device__ float g_qkv[NVOX * 384];     // [v][384]  q|k|v
__device__ float g_attn[NVOX * CDIM];   // [v][128]  attention output
__device__ float g_wt[CDIM * 384];      // qkv_w transposed: [k][n]
__device__ float g_pt[CDIM * CDIM];     // proj_w transposed: [k][c]

typedef unsigned long long ull;

__device__ __forceinline__ ull pack2(float x, float y) {
    ull r; asm("mov.b64 %0, {%1,%2};" : "=l"(r) : "f"(x), "f"(y)); return r;
}
__device__ __forceinline__ void unpack2(ull p, float &x, float &y) {
    asm("mov.b64 {%0,%1}, %2;" : "=f"(x), "=f"(y) : "l"(p));
}
__device__ __forceinline__ ull ffma2(ull a, ull b, ull c) {
    ull d; asm("fma.rn.f32x2 %0, %1, %2, %3;" : "=l"(d) : "l"(a), "l"(b), "l"(c)); return d;
}
__device__ __forceinline__ ull fmul2(ull a, ull b) {
    ull d; asm("mul.rn.f32x2 %0, %1, %2;" : "=l"(d) : "l"(a), "l"(b)); return d;
}

// ---------------------------------------------------------------------------
// Kernel 0: transpose weights for coalesced GEMM B-tile loads
// ---------------------------------------------------------------------------
__global__ void wt_kernel(const float* __restrict__ qw, const float* __restrict__ pw) {
    int i = blockIdx.x * 256 + threadIdx.x;
    if (i < CDIM * 384) {            // g_wt[k][n] = qkv_w[n][k]
        int k = i / 384, n = i - k * 384;
        g_wt[i] = qw[n * CDIM + k];
    }
    if (i < CDIM * CDIM) {           // g_pt[k][c] = proj_w[c][k]
        int k = i >> 7, c = i & 127;
        g_pt[i] = pw[c * CDIM + k];
    }
}

// ---------------------------------------------------------------------------
// Kernel 1: LayerNorm + QKV GEMM.  Block = 64 voxels, 256 threads.
// smem: hs[128][68] (LN'd activations, [k][v]), ws[128][128] ([k][n] chunk)
// ---------------------------------------------------------------------------
__global__ void __launch_bounds__(256) lnqkv_kernel(
    const float* __restrict__ x, const float* __restrict__ gam,
    const float* __restrict__ bet, const float* __restrict__ qb)
{
    extern __shared__ float sm[];
    float* hs = sm;                 // 128*68 floats
    float* ws = sm + 128 * 68;      // 128*128 floats
    const int tid = threadIdx.x;
    const int vb = blockIdx.x * 64;

    // load x tile: hs[c][j] = x[c][vb+j]  (coalesced in j)
    for (int i = tid; i < 128 * 64; i += 256) {
        int c = i >> 6, j = i & 63;
        hs[c * 68 + j] = x[c * NVOX + vb + j];
    }
    __syncthreads();

    // LayerNorm: 4 threads per voxel
    {
        int j = tid >> 2, q = tid & 3;
        float s = 0.f, s2 = 0.f;
        for (int c = q; c < 128; c += 4) { float v = hs[c * 68 + j]; s += v; s2 += v * v; }
        s  += __shfl_xor_sync(0xffffffffu, s, 1);  s  += __shfl_xor_sync(0xffffffffu, s, 2);
        s2 += __shfl_xor_sync(0xffffffffu, s2, 1); s2 += __shfl_xor_sync(0xffffffffu, s2, 2);
        float mu  = s * (1.f / 128.f);
        float var = s2 * (1.f / 128.f) - mu * mu;
        float rs  = rsqrtf(var + 1e-5f);
        for (int c = q; c < 128; c += 4) {
            float v = hs[c * 68 + j];
            hs[c * 68 + j] = (v - mu) * rs * gam[c] + bet[c];
        }
    }

    const int tv = tid & 15, tn = tid >> 4;

    for (int ch = 0; ch < 3; ch++) {
        __syncthreads();
        for (int i = tid; i < 128 * 128; i += 256) {
            int k = i >> 7, n = i & 127;
            ws[i] = g_wt[k * 384 + ch * 128 + n];
        }
        __syncthreads();

        ull acc[4][4];
        {
            const float* qbp = qb + ch * 128 + tn * 8;
            #pragma unroll
            for (int p = 0; p < 4; p++) {
                ull t = pack2(qbp[2 * p], qbp[2 * p + 1]);
                acc[0][p] = t; acc[1][p] = t; acc[2][p] = t; acc[3][p] = t;
            }
        }

        #pragma unroll 8
        for (int k = 0; k < 128; k++) {
            float4 a = *(const float4*)&hs[k * 68 + tv * 4];
            ulonglong2 b0 = *(const ulonglong2*)&ws[k * 128 + tn * 8];
            ulonglong2 b1 = *(const ulonglong2*)&ws[k * 128 + tn * 8 + 4];
            ull a0 = pack2(a.x, a.x), a1 = pack2(a.y, a.y);
            ull a2 = pack2(a.z, a.z), a3 = pack2(a.w, a.w);
            acc[0][0]=ffma2(a0,b0.x,acc[0][0]); acc[0][1]=ffma2(a0,b0.y,acc[0][1]);
            acc[0][2]=ffma2(a0,b1.x,acc[0][2]); acc[0][3]=ffma2(a0,b1.y,acc[0][3]);
            acc[1][0]=ffma2(a1,b0.x,acc[1][0]); acc[1][1]=ffma2(a1,b0.y,acc[1][1]);
            acc[1][2]=ffma2(a1,b1.x,acc[1][2]); acc[1][3]=ffma2(a1,b1.y,acc[1][3]);
            acc[2][0]=ffma2(a2,b0.x,acc[2][0]); acc[2][1]=ffma2(a2,b0.y,acc[2][1]);
            acc[2][2]=ffma2(a2,b1.x,acc[2][2]); acc[2][3]=ffma2(a2,b1.y,acc[2][3]);
            acc[3][0]=ffma2(a3,b0.x,acc[3][0]); acc[3][1]=ffma2(a3,b0.y,acc[3][1]);
            acc[3][2]=ffma2(a3,b1.x,acc[3][2]); acc[3][3]=ffma2(a3,b1.y,acc[3][3]);
        }

        #pragma unroll
        for (int i = 0; i < 4; i++) {
            float o[8];
            #pragma unroll
            for (int p = 0; p < 4; p++) unpack2(acc[i][p], o[2 * p], o[2 * p + 1]);
            float4* dst = (float4*)&g_qkv[(vb + tv * 4 + i) * 384 + ch * 128 + tn * 8];
            dst[0] = make_float4(o[0], o[1], o[2], o[3]);
            dst[1] = make_float4(o[4], o[5], o[6], o[7]);
        }
    }
}

// ---------------------------------------------------------------------------
// Kernel 2: 27-neighbor attention. Block = 4x4x4 spatial tile, all 4 heads.
// smem: ks[216][128], vs[216][128] with XOR swizzle on 16B chunks (221184 B)
// Thread = (head, voxel): tid -> voxel j = tid&63, head h = tid>>6
// ---------------------------------------------------------------------------
__global__ void __launch_bounds__(256) attn_kernel() {
    extern __shared__ float sm[];
    float* ks = sm;                  // 216*128
    float* vs = sm + 216 * 128;
    const int tid = threadIdx.x;
    const int b = blockIdx.x;
    const int tx = b >> 6, ty = (b >> 3) & 7, tz = b & 7;
    const int hx0 = tx * 4 - 1, hy0 = ty * 4 - 1, hz0 = tz * 4 - 1;

    // Load K/V halo (6x6x6 positions x 128 channels each)
    for (int i = tid; i < 216 * 32; i += 256) {
        int p = i >> 5, c4 = i & 31;
        int hx = p / 36, r = p - hx * 36, hy = r / 6, hz = r - hy * 6;
        int gx = min(max(hx0 + hx, 0), 31);
        int gy = min(max(hy0 + hy, 0), 31);
        int gz = min(max(hz0 + hz, 0), 31);
        int gv = (gx << 10) + (gy << 5) + gz;
        float4 kk = *(const float4*)&g_qkv[gv * 384 + 128 + c4 * 4];
        float4 vv = *(const float4*)&g_qkv[gv * 384 + 256 + c4 * 4];
        int h = c4 >> 3, d4 = c4 & 7;
        int col = h * 32 + (((d4 ^ p) & 7) << 2);   // XOR swizzle
        *(float4*)&ks[p * 128 + col] = kk;
        *(float4*)&vs[p * 128 + col] = vv;
    }
    __syncthreads();

    const int j = tid & 63, h = tid >> 6;
    const int lx = j >> 4, ly = (j >> 2) & 3, lz = j & 3;
    const int gx = tx * 4 + lx, gy = ty * 4 + ly, gz = tz * 4 + lz;
    const int gv0 = (gx << 10) + (gy << 5) + gz;
    const int hb = h * 32;

    // Load q (pre-scaled), packed as f32x2 pairs
    ull q2[16];
    {
        const ull s2 = pack2(SCALE, SCALE);
        const ulonglong2* qp = (const ulonglong2*)&g_qkv[gv0 * 384 + hb];
        #pragma unroll
        for (int c = 0; c < 8; c++) {
            ulonglong2 t = qp[c];
            q2[2 * c]     = fmul2(t.x, s2);
            q2[2 * c + 1] = fmul2(t.y, s2);
        }
    }

    const int sx = min(max(gx - 1, 0), 29) - hx0;
    const int sy = min(max(gy - 1, 0), 29) - hy0;
    const int sz = min(max(gz - 1, 0), 29) - hz0;

    float sc[27];
    #pragma unroll
    for (int dx = 0; dx < 3; dx++)
    #pragma unroll
    for (int dy = 0; dy < 3; dy++)
    #pragma unroll
    for (int dz = 0; dz < 3; dz++) {
        int p = (sx + dx) * 36 + (sy + dy) * 6 + (sz + dz);
        int base = p * 128 + hb;
        int sw = p & 7;
        ull a0 = 0ull, a1 = 0ull;
        #pragma unroll
        for (int d4 = 0; d4 < 8; d4++) {
            ulonglong2 kk = *(const ulonglong2*)&ks[base + ((d4 ^ sw) << 2)];
            a0 = ffma2(q2[2 * d4], kk.x, a0);
            a1 = ffma2(q2[2 * d4 + 1], kk.y, a1);
        }
        float e0, e1, e2, e3;
        unpack2(a0, e0, e1); unpack2(a1, e2, e3);
        sc[dx * 9 + dy * 3 + dz] = (e0 + e1) + (e2 + e3);
    }

    // Softmax over 27
    float mx = sc[0];
    #pragma unroll
    for (int n = 1; n < 27; n++) mx = fmaxf(mx, sc[n]);
    float sum = 0.f;
    #pragma unroll
    for (int n = 0; n < 27; n++) { float e = __expf(sc[n] - mx); sc[n] = e; sum += e; }
    float inv = __fdividef(1.f, sum);

    // Weighted sum of V
    ull o2[16];
    #pragma unroll
    for (int i = 0; i < 16; i++) o2[i] = 0ull;

    #pragma unroll
    for (int dx = 0; dx < 3; dx++)
    #pragma unroll
    for (int dy = 0; dy < 3; dy++)
    #pragma unroll
    for (int dz = 0; dz < 3; dz++) {
        int p = (sx + dx) * 36 + (sy + dy) * 6 + (sz + dz);
        int base = p * 128 + hb;
        int sw = p & 7;
        float w = sc[dx * 9 + dy * 3 + dz];
        ull w2 = pack2(w, w);
        #pragma unroll
        for (int d4 = 0; d4 < 8; d4++) {
            ulonglong2 vv = *(const ulonglong2*)&vs[base + ((d4 ^ sw) << 2)];
            o2[2 * d4]     = ffma2(w2, vv.x, o2[2 * d4]);
            o2[2 * d4 + 1] = ffma2(w2, vv.y, o2[2 * d4 + 1]);
        }
    }

    float* op = &g_attn[gv0 * 128 + hb];
    #pragma unroll
    for (int c = 0; c < 8; c++) {
        float f0, f1, f2, f3;
        unpack2(o2[2 * c], f0, f1);
        unpack2(o2[2 * c + 1], f2, f3);
        *(float4*)&op[4 * c] = make_float4(f0 * inv, f1 * inv, f2 * inv, f3 * inv);
    }
}

// ---------------------------------------------------------------------------
// Kernel 3: proj GEMM + bias + residual.  Block = 64 voxels, 256 threads.
// out[c][v] = sum_k attn[v][k] * proj_w[c][k] + pb[c] + x[c][v]
// ---------------------------------------------------------------------------
__global__ void __launch_bounds__(256) proj_kernel(
    const float* __restrict__ x, const float* __restrict__ pb, float* __restrict__ out)
{
    extern __shared__ float sm[];
    float* as_ = sm;                // 128*68  [k][v]
    float* ws  = sm + 128 * 68;     // 128*128 [k][c]
    const int tid = threadIdx.x;
    const int vb = blockIdx.x * 64;

    for (int i = tid; i < 128 * 64; i += 256) {
        int j = i >> 7, c = i & 127;
        as_[c * 68 + j] = g_attn[(vb + j) * 128 + c];
    }
    for (int i = tid; i < 128 * 128; i += 256) ws[i] = g_pt[i];
    __syncthreads();

    const int tv = tid & 15, tn = tid >> 4;

    ull acc[4][4];
    {
        const float* pbp = pb + tn * 8;
        #pragma unroll
        for (int p = 0; p < 4; p++) {
            ull t = pack2(pbp[2 * p], pbp[2 * p + 1]);
            acc[0][p] = t; acc[1][p] = t; acc[2][p] = t; acc[3][p] = t;
        }
    }

    #pragma unroll 8
    for (int k = 0; k < 128; k++) {
        float4 a = *(const float4*)&as_[k * 68 + tv * 4];
        ulonglong2 b0 = *(const ulonglong2*)&ws[k * 128 + tn * 8];
        ulonglong2 b1 = *(const ulonglong2*)&ws[k * 128 + tn * 8 + 4];
        ull a0 = pack2(a.x, a.x), a1 = pack2(a.y, a.y);
        ull a2 = pack2(a.z, a.z), a3 = pack2(a.w, a.w);
        acc[0][0]=ffma2(a0,b0.x,acc[0][0]); acc[0][1]=ffma2(a0,b0.y,acc[0][1]);
        acc[0][2]=ffma2(a0,b1.x,acc[0][2]); acc[0][3]=ffma2(a0,b1.y,acc[0][3]);
        acc[1][0]=ffma2(a1,b0.x,acc[1][0]); acc[1][1]=ffma2(a1,b0.y,acc[1][1]);
        acc[1][2]=ffma2(a1,b1.x,acc[1][2]); acc[1][3]=ffma2(a1,b1.y,acc[1][3]);
        acc[2][0]=ffma2(a2,b0.x,acc[2][0]); acc[2][1]=ffma2(a2,b0.y,acc[2][1]);
        acc[2][2]=ffma2(a2,b1.x,acc[2][2]); acc[2][3]=ffma2(a2,b1.y,acc[2][3]);
        acc[3][0]=ffma2(a3,b0.x,acc[3][0]); acc[3][1]=ffma2(a3,b0.y,acc[3][1]);
        acc[3][2]=ffma2(a3,b1.x,acc[3][2]); acc[3][3]=ffma2(a3,b1.y,acc[3][3]);
    }

    // Unpack: r[i][cc] = out for voxel (vb+tv*4+i), channel (tn*8+cc)
    float r[4][8];
    #pragma unroll
    for (int i = 0; i < 4; i++)
        #pragma unroll
        for (int p = 0; p < 4; p++) unpack2(acc[i][p], r[i][2 * p], r[i][2 * p + 1]);

    #pragma unroll
    for (int cc = 0; cc < 8; cc++) {
        int c = tn * 8 + cc;
        int off = c * NVOX + vb + tv * 4;
        float4 xr = *(const float4*)&x[off];
        *(float4*)&out[off] = make_float4(r[0][cc] + xr.x, r[1][cc] + xr.y,
                                          r[2][cc] + xr.z, r[3][cc] + xr.w);
    }
}

// ---------------------------------------------------------------------------
extern "C" void kernel_launch(void* const* d_in, const int* in_sizes, int n_in,
                              void* d_out, int out_size)
{
    const float* x   = (const float*)d_in[0];
    const float* gam = (const float*)d_in[1];
    const float* bet = (const float*)d_in[2];
    const float* qw  = (const float*)d_in[3];
    const float* qb  = (const float*)d_in[4];
    const float* pw  = (const float*)d_in[5];
    const float* pb  = (const float*)d_in[6];
    float* out = (float*)d_out;

    const int SMEM_GEMM = (128 * 68 + 128 * 128) * 4;   // 100352
    const int SMEM_ATTN = 216 * 128 * 2 * 4;            // 221184

    cudaFuncSetAttribute(lnqkv_kernel, cudaFuncAttributeMaxDynamicSharedMemorySize, SMEM_GEMM);
    cudaFuncSetAttribute(attn_kernel,  cudaFuncAttributeMaxDynamicSharedMemorySize, SMEM_ATTN);
    cudaFuncSetAttribute(proj_kernel,  cudaFuncAttributeMaxDynamicSharedMemorySize, SMEM_GEMM);

    wt_kernel<<<192, 256>>>(qw, pw);
    lnqkv_kernel<<<512, 256, SMEM_GEMM>>>(x, gam, bet, qb);
    attn_kernel<<<512, 256, SMEM_ATTN>>>();
    proj_kernel<<<512, 256, SMEM_GEMM>>>(x, pb, out);
}

// round 2
// speedup vs baseline: 1.0148x; 1.0148x over previous
#include <cuda_runtime.h>

#define NVOX 32768      // 32*32*32
#define SCALE 0.17677669529663689f   // 1/sqrt(32)

// Scratch (allocation-free: device globals)
__device__ float g_qkv[NVOX * 384];     // [v][384]  q|k|v
__device__ float g_attn[128 * NVOX];    // [c][v]    attention output (channel-major)
__device__ float g_wt[128 * 384];       // qkv_w transposed: [k][n]
__device__ float g_pt[128 * 128];       // proj_w transposed: [k][c]

typedef unsigned long long ull;

__device__ __forceinline__ ull pack2(float x, float y) {
    ull r; asm("mov.b64 %0, {%1,%2};" : "=l"(r) : "f"(x), "f"(y)); return r;
}
__device__ __forceinline__ ull dup2(float x) {
    ull r; asm("mov.b64 %0, {%1,%1};" : "=l"(r) : "f"(x)); return r;
}
__device__ __forceinline__ void unpack2(ull p, float &x, float &y) {
    asm("mov.b64 {%0,%1}, %2;" : "=f"(x), "=f"(y) : "l"(p));
}
__device__ __forceinline__ ull ffma2(ull a, ull b, ull c) {
    ull d; asm("fma.rn.f32x2 %0, %1, %2, %3;" : "=l"(d) : "l"(a), "l"(b), "l"(c)); return d;
}
__device__ __forceinline__ ull fmul2(ull a, ull b) {
    ull d; asm("mul.rn.f32x2 %0, %1, %2;" : "=l"(d) : "l"(a), "l"(b)); return d;
}

// ---------------------------------------------------------------------------
// Kernel 0: transpose weights
// ---------------------------------------------------------------------------
__global__ void wt_kernel(const float* __restrict__ qw, const float* __restrict__ pw) {
    int i = blockIdx.x * 256 + threadIdx.x;
    if (i < 128 * 384) {             // g_wt[k][n] = qkv_w[n][k]
        int k = i / 384, n = i - k * 384;
        g_wt[i] = qw[n * 128 + k];
    }
    if (i < 128 * 128) {             // g_pt[k][c] = proj_w[c][k]
        int k = i >> 7, c = i & 127;
        g_pt[i] = pw[c * 128 + k];
    }
}

// ---------------------------------------------------------------------------
// GEMM microkernel: per-thread 8v x 8n tile, f32x2 paired along v.
// acc[p][n] packs voxels (2p, 2p+1) for channel n.
// ---------------------------------------------------------------------------
__device__ __forceinline__ void mma_8x8(ull acc[4][8], const float* __restrict__ hs_row,
                                        const float* __restrict__ ws_row, int tv, int tn)
{
    ulonglong2 a01 = *(const ulonglong2*)(hs_row + tv * 8);
    ulonglong2 a23 = *(const ulonglong2*)(hs_row + tv * 8 + 4);
    float4 b0 = *(const float4*)(ws_row + tn * 8);
    float4 b1 = *(const float4*)(ws_row + tn * 8 + 4);
    ull bd[8];
    bd[0] = dup2(b0.x); bd[1] = dup2(b0.y); bd[2] = dup2(b0.z); bd[3] = dup2(b0.w);
    bd[4] = dup2(b1.x); bd[5] = dup2(b1.y); bd[6] = dup2(b1.z); bd[7] = dup2(b1.w);
    #pragma unroll
    for (int n = 0; n < 8; n++) {
        acc[0][n] = ffma2(a01.x, bd[n], acc[0][n]);
        acc[1][n] = ffma2(a01.y, bd[n], acc[1][n]);
        acc[2][n] = ffma2(a23.x, bd[n], acc[2][n]);
        acc[3][n] = ffma2(a23.y, bd[n], acc[3][n]);
    }
}

// ---------------------------------------------------------------------------
// Kernel 1: LayerNorm + QKV GEMM.  Block = 128 voxels, 256 threads, 2 blocks/SM.
// smem: hs[128][128] (LN'd activations, [k][v]) + ws[64][128] (k-chunk of weights)
// ---------------------------------------------------------------------------
__global__ void __launch_bounds__(256, 2) lnqkv_kernel(
    const float* __restrict__ x, const float* __restrict__ gam,
    const float* __restrict__ bet, const float* __restrict__ qb)
{
    extern __shared__ float sm[];
    float* hs = sm;                 // 128*128
    float* ws = sm + 128 * 128;     // 64*128
    const int tid = threadIdx.x;
    const int vb = blockIdx.x * 128;

    // stage x tile: hs[c][j] = x[c][vb+j], fully coalesced float4
    for (int i = tid; i < 128 * 32; i += 256) {
        int c = i >> 5, q = i & 31;
        *(float4*)&hs[c * 128 + q * 4] = *(const float4*)&x[c * NVOX + vb + q * 4];
    }
    __syncthreads();

    // LayerNorm: 2 threads per voxel
    {
        int j = tid >> 1, q = tid & 1;
        float s = 0.f, s2 = 0.f;
        for (int c = q; c < 128; c += 2) { float v = hs[c * 128 + j]; s += v; s2 += v * v; }
        s  += __shfl_xor_sync(0xffffffffu, s, 1);
        s2 += __shfl_xor_sync(0xffffffffu, s2, 1);
        float mu  = s * (1.f / 128.f);
        float var = s2 * (1.f / 128.f) - mu * mu;
        float rs  = rsqrtf(var + 1e-5f);
        for (int c = q; c < 128; c += 2) {
            float v = hs[c * 128 + j];
            hs[c * 128 + j] = (v - mu) * rs * gam[c] + bet[c];
        }
    }

    const int tv = tid & 15, tn = tid >> 4;

    for (int ch = 0; ch < 3; ch++) {
        ull acc[4][8];
        #pragma unroll
        for (int p = 0; p < 4; p++)
            #pragma unroll
            for (int n = 0; n < 8; n++) acc[p][n] = 0ull;

        #pragma unroll
        for (int kc = 0; kc < 2; kc++) {
            __syncthreads();
            for (int i = tid; i < 64 * 32; i += 256) {
                int kk = i >> 5, q = i & 31;
                *(float4*)&ws[kk * 128 + q * 4] =
                    *(const float4*)&g_wt[(kc * 64 + kk) * 384 + ch * 128 + q * 4];
            }
            __syncthreads();
            #pragma unroll 4
            for (int kk = 0; kk < 64; kk++) {
                mma_8x8(acc, &hs[(kc * 64 + kk) * 128], &ws[kk * 128], tv, tn);
            }
        }

        // epilogue: bias + store to g_qkv[v][384]
        float bias[8];
        #pragma unroll
        for (int n = 0; n < 8; n++) bias[n] = qb[ch * 128 + tn * 8 + n];

        #pragma unroll
        for (int p = 0; p < 4; p++) {
            float lo[8], hi[8];
            #pragma unroll
            for (int n = 0; n < 8; n++) { unpack2(acc[p][n], lo[n], hi[n]); lo[n] += bias[n]; hi[n] += bias[n]; }
            float* d0 = &g_qkv[(vb + tv * 8 + 2 * p) * 384 + ch * 128 + tn * 8];
            float* d1 = d0 + 384;
            *(float4*)(d0)     = make_float4(lo[0], lo[1], lo[2], lo[3]);
            *(float4*)(d0 + 4) = make_float4(lo[4], lo[5], lo[6], lo[7]);
            *(float4*)(d1)     = make_float4(hi[0], hi[1], hi[2], hi[3]);
            *(float4*)(d1 + 4) = make_float4(hi[4], hi[5], hi[6], hi[7]);
        }
    }
}

// ---------------------------------------------------------------------------
// Kernel 2: 27-neighbor attention, two-phase (K then V) in one 110KB buffer.
// Block = 4x4x4 spatial tile x 4 heads, 256 threads, 2 blocks/SM.
// ---------------------------------------------------------------------------
__global__ void __launch_bounds__(256, 2) attn_kernel() {
    extern __shared__ float sm[];
    float* buf = sm;                 // 216*128 floats, swizzled
    const int tid = threadIdx.x;
    const int b = blockIdx.x;
    const int tx = b >> 6, ty = (b >> 3) & 7, tz = b & 7;
    const int hx0 = tx * 4 - 1, hy0 = ty * 4 - 1, hz0 = tz * 4 - 1;

    const int j = tid & 63, h = tid >> 6;
    const int lx = j >> 4, ly = (j >> 2) & 3, lz = j & 3;
    const int gx = tx * 4 + lx, gy = ty * 4 + ly, gz = tz * 4 + lz;
    const int gv0 = (gx << 10) + (gy << 5) + gz;
    const int hb = h * 32;

    // ---- Phase K: load K halo ----
    for (int i = tid; i < 216 * 32; i += 256) {
        int p = i >> 5, c4 = i & 31;
        int hx = p / 36, r = p - hx * 36, hy = r / 6, hz = r - hy * 6;
        int ggx = min(max(hx0 + hx, 0), 31);
        int ggy = min(max(hy0 + hy, 0), 31);
        int ggz = min(max(hz0 + hz, 0), 31);
        int gv = (ggx << 10) + (ggy << 5) + ggz;
        float4 kk = *(const float4*)&g_qkv[gv * 384 + 128 + c4 * 4];
        int hh = c4 >> 3, d4 = c4 & 7;
        int col = hh * 32 + (((d4 ^ p) & 7) << 2);   // XOR swizzle
        *(float4*)&buf[p * 128 + col] = kk;
    }

    // q (pre-scaled) while K streams in
    ull q2[16];
    {
        const ull s2 = pack2(SCALE, SCALE);
        const ulonglong2* qp = (const ulonglong2*)&g_qkv[gv0 * 384 + hb];
        #pragma unroll
        for (int c = 0; c < 8; c++) {
            ulonglong2 t = qp[c];
            q2[2 * c]     = fmul2(t.x, s2);
            q2[2 * c + 1] = fmul2(t.y, s2);
        }
    }
    __syncthreads();

    const int sx = min(max(gx - 1, 0), 29) - hx0;
    const int sy = min(max(gy - 1, 0), 29) - hy0;
    const int sz = min(max(gz - 1, 0), 29) - hz0;

    float sc[27];
    #pragma unroll
    for (int dx = 0; dx < 3; dx++)
    #pragma unroll
    for (int dy = 0; dy < 3; dy++)
    #pragma unroll
    for (int dz = 0; dz < 3; dz++) {
        int p = (sx + dx) * 36 + (sy + dy) * 6 + (sz + dz);
        int base = p * 128 + hb;
        int sw = p & 7;
        ull a0 = 0ull, a1 = 0ull;
        #pragma unroll
        for (int d4 = 0; d4 < 8; d4++) {
            ulonglong2 kk = *(const ulonglong2*)&buf[base + ((d4 ^ sw) << 2)];
            a0 = ffma2(q2[2 * d4], kk.x, a0);
            a1 = ffma2(q2[2 * d4 + 1], kk.y, a1);
        }
        float e0, e1, e2, e3;
        unpack2(a0, e0, e1); unpack2(a1, e2, e3);
        sc[dx * 9 + dy * 3 + dz] = (e0 + e1) + (e2 + e3);
    }

    // Softmax over 27
    float mx = sc[0];
    #pragma unroll
    for (int n = 1; n < 27; n++) mx = fmaxf(mx, sc[n]);
    float sum = 0.f;
    #pragma unroll
    for (int n = 0; n < 27; n++) { float e = __expf(sc[n] - mx); sc[n] = e; sum += e; }
    float inv = __fdividef(1.f, sum);

    // ---- Phase V: overwrite buffer with V halo ----
    __syncthreads();
    for (int i = tid; i < 216 * 32; i += 256) {
        int p = i >> 5, c4 = i & 31;
        int hx = p / 36, r = p - hx * 36, hy = r / 6, hz = r - hy * 6;
        int ggx = min(max(hx0 + hx, 0), 31);
        int ggy = min(max(hy0 + hy, 0), 31);
        int ggz = min(max(hz0 + hz, 0), 31);
        int gv = (ggx << 10) + (ggy << 5) + ggz;
        float4 vv = *(const float4*)&g_qkv[gv * 384 + 256 + c4 * 4];
        int hh = c4 >> 3, d4 = c4 & 7;
        int col = hh * 32 + (((d4 ^ p) & 7) << 2);
        *(float4*)&buf[p * 128 + col] = vv;
    }
    __syncthreads();

    // Weighted sum of V
    ull o2[16];
    #pragma unroll
    for (int i = 0; i < 16; i++) o2[i] = 0ull;

    #pragma unroll
    for (int dx = 0; dx < 3; dx++)
    #pragma unroll
    for (int dy = 0; dy < 3; dy++)
    #pragma unroll
    for (int dz = 0; dz < 3; dz++) {
        int p = (sx + dx) * 36 + (sy + dy) * 6 + (sz + dz);
        int base = p * 128 + hb;
        int sw = p & 7;
        float w = sc[dx * 9 + dy * 3 + dz];
        ull w2 = pack2(w, w);
        #pragma unroll
        for (int d4 = 0; d4 < 8; d4++) {
            ulonglong2 vv = *(const ulonglong2*)&buf[base + ((d4 ^ sw) << 2)];
            o2[2 * d4]     = ffma2(w2, vv.x, o2[2 * d4]);
            o2[2 * d4 + 1] = ffma2(w2, vv.y, o2[2 * d4 + 1]);
        }
    }

    // Store channel-major: g_attn[c][v]
    #pragma unroll
    for (int c = 0; c < 16; c++) {
        float f0, f1;
        unpack2(o2[c], f0, f1);
        g_attn[(hb + 2 * c) * NVOX + gv0]     = f0 * inv;
        g_attn[(hb + 2 * c + 1) * NVOX + gv0] = f1 * inv;
    }
}

// ---------------------------------------------------------------------------
// Kernel 3: proj GEMM + bias + residual.  Block = 128 voxels, 256 threads, 2/SM.
// out[c][v] = sum_k attn[k][v] * g_pt[k][c] + pb[c] + x[c][v]
// ---------------------------------------------------------------------------
__global__ void __launch_bounds__(256, 2) proj_kernel(
    const float* __restrict__ x, const float* __restrict__ pb, float* __restrict__ out)
{
    extern __shared__ float sm[];
    float* as_ = sm;                // 128*128  [k][v]
    float* ws  = sm + 128 * 128;    // 64*128   [k][c] chunk
    const int tid = threadIdx.x;
    const int vb = blockIdx.x * 128;

    // stage A: g_attn is channel-major -> no transpose, coalesced float4
    for (int i = tid; i < 128 * 32; i += 256) {
        int c = i >> 5, q = i & 31;
        *(float4*)&as_[c * 128 + q * 4] = *(const float4*)&g_attn[c * NVOX + vb + q * 4];
    }

    const int tv = tid & 15, tn = tid >> 4;

    ull acc[4][8];
    #pragma unroll
    for (int p = 0; p < 4; p++)
        #pragma unroll
        for (int n = 0; n < 8; n++) acc[p][n] = 0ull;

    #pragma unroll
    for (int kc = 0; kc < 2; kc++) {
        __syncthreads();
        for (int i = tid; i < 64 * 32; i += 256) {
            int kk = i >> 5, q = i & 31;
            *(float4*)&ws[kk * 128 + q * 4] =
                *(const float4*)&g_pt[(kc * 64 + kk) * 128 + q * 4];
        }
        __syncthreads();
        #pragma unroll 4
        for (int kk = 0; kk < 64; kk++) {
            mma_8x8(acc, &as_[(kc * 64 + kk) * 128], &ws[kk * 128], tv, tn);
        }
    }

    // epilogue: bias + residual, coalesced channel-major stores
    #pragma unroll
    for (int n = 0; n < 8; n++) {
        int c = tn * 8 + n;
        float bias = pb[c];
        float v0, v1, v2, v3, v4, v5, v6, v7;
        unpack2(acc[0][n], v0, v1); unpack2(acc[1][n], v2, v3);
        unpack2(acc[2][n], v4, v5); unpack2(acc[3][n], v6, v7);
        int off = c * NVOX + vb + tv * 8;
        float4 x0 = *(const float4*)&x[off];
        float4 x1 = *(const float4*)&x[off + 4];
        *(float4*)&out[off]     = make_float4(v0 + bias + x0.x, v1 + bias + x0.y,
                                              v2 + bias + x0.z, v3 + bias + x0.w);
        *(float4*)&out[off + 4] = make_float4(v4 + bias + x1.x, v5 + bias + x1.y,
                                              v6 + bias + x1.z, v7 + bias + x1.w);
    }
}

// ---------------------------------------------------------------------------
extern "C" void kernel_launch(void* const* d_in, const int* in_sizes, int n_in,
                              void* d_out, int out_size)
{
    const float* x   = (const float*)d_in[0];
    const float* gam = (const float*)d_in[1];
    const float* bet = (const float*)d_in[2];
    const float* qw  = (const float*)d_in[3];
    const float* qb  = (const float*)d_in[4];
    const float* pw  = (const float*)d_in[5];
    const float* pb  = (const float*)d_in[6];
    float* out = (float*)d_out;

    const int SMEM_GEMM = (128 * 128 + 64 * 128) * 4;   // 98304
    const int SMEM_ATTN = 216 * 128 * 4;                // 110592

    cudaFuncSetAttribute(lnqkv_kernel, cudaFuncAttributeMaxDynamicSharedMemorySize, SMEM_GEMM);
    cudaFuncSetAttribute(attn_kernel,  cudaFuncAttributeMaxDynamicSharedMemorySize, SMEM_ATTN);
    cudaFuncSetAttribute(proj_kernel,  cudaFuncAttributeMaxDynamicSharedMemorySize, SMEM_GEMM);

    wt_kernel<<<192, 256>>>(qw, pw);
    lnqkv_kernel<<<256, 256, SMEM_GEMM>>>(x, gam, bet, qb);
    attn_kernel<<<512, 256, SMEM_ATTN>>>();
    proj_kernel<<<256, 256, SMEM_GEMM>>>(x, pb, out);
}

// round 4
// speedup vs baseline: 1.1331x; 1.1165x over previous
#include <cuda_runtime.h>
#include <cuda_bf16.h>
#include <cstdint>

#define NVOX 32768
#define SCALE 0.17677669529663689f   // 1/sqrt(32)

// Scratch (allocation-free: device globals)
__device__ float g_qkv[NVOX * 384];     // [v][384]  q|k|v
__device__ float g_attn[128 * NVOX];    // [c][v]    attention output (channel-major)

typedef unsigned long long ull;

// ---------------------------------------------------------------------------
// helpers
// ---------------------------------------------------------------------------
__device__ __forceinline__ ull pack2(float x, float y) {
    ull r; asm("mov.b64 %0, {%1,%2};" : "=l"(r) : "f"(x), "f"(y)); return r;
}
__device__ __forceinline__ void unpack2(ull p, float &x, float &y) {
    asm("mov.b64 {%0,%1}, %2;" : "=f"(x), "=f"(y) : "l"(p));
}
__device__ __forceinline__ ull ffma2(ull a, ull b, ull c) {
    ull d; asm("fma.rn.f32x2 %0, %1, %2, %3;" : "=l"(d) : "l"(a), "l"(b), "l"(c)); return d;
}
__device__ __forceinline__ ull fmul2(ull a, ull b) {
    ull d; asm("mul.rn.f32x2 %0, %1, %2;" : "=l"(d) : "l"(a), "l"(b)); return d;
}

// warp mma: D(16x8,f32) += A(16x16 bf16,row) * B(16x8 bf16,col)
__device__ __forceinline__ void mma16816(float* d, const uint32_t* a, const uint32_t* b) {
    asm volatile(
        "mma.sync.aligned.m16n8k16.row.col.f32.bf16.bf16.f32 "
        "{%0,%1,%2,%3}, {%4,%5,%6,%7}, {%8,%9}, {%0,%1,%2,%3};"
        : "+f"(d[0]), "+f"(d[1]), "+f"(d[2]), "+f"(d[3])
        : "r"(a[0]), "r"(a[1]), "r"(a[2]), "r"(a[3]), "r"(b[0]), "r"(b[1]));
}

// split-convert 8 fp32 -> 8 bf16 hi + 8 bf16 lo, packed as uint4 each
__device__ __forceinline__ void split8(const float* v, uint4& hi, uint4& lo) {
    uint32_t h[4], l[4];
    #pragma unroll
    for (int i = 0; i < 4; i++) {
        __nv_bfloat16 h0 = __float2bfloat16_rn(v[2 * i]);
        __nv_bfloat16 h1 = __float2bfloat16_rn(v[2 * i + 1]);
        __nv_bfloat16 l0 = __float2bfloat16_rn(v[2 * i]     - __bfloat162float(h0));
        __nv_bfloat16 l1 = __float2bfloat16_rn(v[2 * i + 1] - __bfloat162float(h1));
        h[i] = (uint32_t)__bfloat16_as_ushort(h0) | ((uint32_t)__bfloat16_as_ushort(h1) << 16);
        l[i] = (uint32_t)__bfloat16_as_ushort(l0) | ((uint32_t)__bfloat16_as_ushort(l1) << 16);
    }
    hi = make_uint4(h[0], h[1], h[2], h[3]);
    lo = make_uint4(l[0], l[1], l[2], l[3]);
}

// smem tile geometry: [row][k] bf16, padded row stride 136 (272 B) -> conflict-free frags
#define TSTRIDE 136
#define TILE_BYTES (128 * TSTRIDE * 2)   // 34816
#define OFF_AH 0
#define OFF_AL TILE_BYTES
#define OFF_BH (2 * TILE_BYTES)
#define OFF_BL (3 * TILE_BYTES)
#define SMEM_MMA (4 * TILE_BYTES)        // 139264

// load A fragments (one m16 tile) for k-block ks
__device__ __forceinline__ void load_afrag(uint32_t* f, const char* base, int row, int ks, int t2) {
    const char* p = base + row * (TSTRIDE * 2) + ks * 32 + t2 * 4;
    f[0] = *(const uint32_t*)(p);
    f[1] = *(const uint32_t*)(p + 8 * TSTRIDE * 2);
    f[2] = *(const uint32_t*)(p + 16);
    f[3] = *(const uint32_t*)(p + 8 * TSTRIDE * 2 + 16);
}

// ---------------------------------------------------------------------------
// GEMM mainloop: A[128][128] x B[128][128]^T(K-major rows) -> acc frags
// warp grid 4(m) x 2(n); warp tile 32v x 64n; acc[mt2][nt8][4]
// ---------------------------------------------------------------------------
__device__ __forceinline__ void mma_mainloop(float acc[2][8][4], const char* smem,
                                             int m0, int n0, int g, int t2)
{
    #pragma unroll
    for (int ks = 0; ks < 8; ks++) {
        uint32_t Afh[2][4], Afl[2][4];
        load_afrag(Afh[0], smem + OFF_AH, m0 + g,      ks, t2);
        load_afrag(Afh[1], smem + OFF_AH, m0 + 16 + g, ks, t2);
        load_afrag(Afl[0], smem + OFF_AL, m0 + g,      ks, t2);
        load_afrag(Afl[1], smem + OFF_AL, m0 + 16 + g, ks, t2);
        #pragma unroll
        for (int nt = 0; nt < 8; nt++) {
            const char* bh = smem + OFF_BH + (n0 + nt * 8 + g) * (TSTRIDE * 2) + ks * 32 + t2 * 4;
            const char* bl = smem + OFF_BL + (n0 + nt * 8 + g) * (TSTRIDE * 2) + ks * 32 + t2 * 4;
            uint32_t Bh[2] = { *(const uint32_t*)bh, *(const uint32_t*)(bh + 16) };
            uint32_t Bl[2] = { *(const uint32_t*)bl, *(const uint32_t*)(bl + 16) };
            mma16816(acc[0][nt], Afh[0], Bh);
            mma16816(acc[1][nt], Afh[1], Bh);
            mma16816(acc[0][nt], Afl[0], Bh);
            mma16816(acc[1][nt], Afl[1], Bh);
            mma16816(acc[0][nt], Afh[0], Bl);
            mma16816(acc[1][nt], Afh[1], Bl);
        }
    }
}

// ---------------------------------------------------------------------------
// Kernel 1: LN (in registers) + QKV GEMM on mma.sync.  CTA = 128 voxels.
// ---------------------------------------------------------------------------
__global__ void __launch_bounds__(256) lnqkv_mma(
    const float* __restrict__ x, const float* __restrict__ gam,
    const float* __restrict__ bet, const float* __restrict__ qw,
    const float* __restrict__ qb)
{
    extern __shared__ char smem[];
    const int tid = threadIdx.x, lane = tid & 31, wid = tid >> 5;
    const int vb = blockIdx.x * 128;

    // ---- LayerNorm in registers: 2 threads per voxel, 64 channels each ----
    {
        const int v = tid >> 1, q = tid & 1;
        float r[64];
        const float* xp = x + (q * 64) * NVOX + vb + v;
        #pragma unroll 8
        for (int i = 0; i < 64; i++) r[i] = xp[i * NVOX];
        float s = 0.f, s2 = 0.f;
        #pragma unroll
        for (int i = 0; i < 64; i++) { s += r[i]; s2 += r[i] * r[i]; }
        s  += __shfl_xor_sync(0xffffffffu, s, 1);
        s2 += __shfl_xor_sync(0xffffffffu, s2, 1);
        float mu = s * (1.f / 128.f);
        float var = s2 * (1.f / 128.f) - mu * mu;
        float rs = rsqrtf(var + 1e-5f);
        #pragma unroll 8
        for (int i = 0; i < 64; i++) {
            int c = q * 64 + i;
            r[i] = (r[i] - mu) * rs * __ldg(&gam[c]) + __ldg(&bet[c]);
        }
        // split-convert -> A tiles [v][k]
        #pragma unroll
        for (int j = 0; j < 8; j++) {
            uint4 hi, lo; split8(&r[8 * j], hi, lo);
            int chunk = q * 8 + j;
            *(uint4*)(smem + OFF_AH + v * (TSTRIDE * 2) + chunk * 16) = hi;
            *(uint4*)(smem + OFF_AL + v * (TSTRIDE * 2) + chunk * 16) = lo;
        }
    }

    const int g = lane >> 2, t2 = lane & 3;
    const int m0 = (wid & 3) * 32, n0 = (wid >> 2) * 64;

    for (int nc = 0; nc < 3; nc++) {
        __syncthreads();   // A ready (first iter) / prev mma done reading B
        // stage B chunk: qkv_w rows [nc*128, +128), K-major native
        #pragma unroll
        for (int t = 0; t < 8; t++) {
            int task = tid + t * 256;
            int n = task >> 4, kc = task & 15;
            float vals[8];
            *(float4*)&vals[0] = *(const float4*)&qw[(nc * 128 + n) * 128 + kc * 8];
            *(float4*)&vals[4] = *(const float4*)&qw[(nc * 128 + n) * 128 + kc * 8 + 4];
            uint4 hi, lo; split8(vals, hi, lo);
            *(uint4*)(smem + OFF_BH + n * (TSTRIDE * 2) + kc * 16) = hi;
            *(uint4*)(smem + OFF_BL + n * (TSTRIDE * 2) + kc * 16) = lo;
        }
        __syncthreads();

        float acc[2][8][4];
        #pragma unroll
        for (int nt = 0; nt < 8; nt++) {
            float b0 = __ldg(&qb[nc * 128 + n0 + nt * 8 + t2 * 2]);
            float b1 = __ldg(&qb[nc * 128 + n0 + nt * 8 + t2 * 2 + 1]);
            acc[0][nt][0] = b0; acc[0][nt][1] = b1; acc[0][nt][2] = b0; acc[0][nt][3] = b1;
            acc[1][nt][0] = b0; acc[1][nt][1] = b1; acc[1][nt][2] = b0; acc[1][nt][3] = b1;
        }

        mma_mainloop(acc, smem, m0, n0, g, t2);

        // epilogue: direct float2 stores to g_qkv[v][384]
        #pragma unroll
        for (int mt = 0; mt < 2; mt++) {
            int row = vb + m0 + mt * 16 + g;
            #pragma unroll
            for (int nt = 0; nt < 8; nt++) {
                int col = nc * 128 + n0 + nt * 8 + t2 * 2;
                *(float2*)&g_qkv[row * 384 + col]       = make_float2(acc[mt][nt][0], acc[mt][nt][1]);
                *(float2*)&g_qkv[(row + 8) * 384 + col] = make_float2(acc[mt][nt][2], acc[mt][nt][3]);
            }
        }
    }
}

// ---------------------------------------------------------------------------
// Kernel 2: 27-neighbor attention (fp32, two-phase K/V in one buffer).
// Block = 4x4x4 spatial tile x 4 heads, 256 threads, 2 blocks/SM.
// ---------------------------------------------------------------------------
__global__ void __launch_bounds__(256, 2) attn_kernel() {
    extern __shared__ float buf[];       // 216*128 floats
    const int tid = threadIdx.x;
    const int b = blockIdx.x;
    const int tx = b >> 6, ty = (b >> 3) & 7, tz = b & 7;
    const int hx0 = tx * 4 - 1, hy0 = ty * 4 - 1, hz0 = tz * 4 - 1;

    const int j = tid & 63, h = tid >> 6;
    const int lx = j >> 4, ly = (j >> 2) & 3, lz = j & 3;
    const int gx = tx * 4 + lx, gy = ty * 4 + ly, gz = tz * 4 + lz;
    const int gv0 = (gx << 10) + (gy << 5) + gz;
    const int hb = h * 32;

    // Phase K
    for (int i = tid; i < 216 * 32; i += 256) {
        int p = i >> 5, c4 = i & 31;
        int hx = p / 36, r = p - hx * 36, hy = r / 6, hz = r - hy * 6;
        int ggx = min(max(hx0 + hx, 0), 31);
        int ggy = min(max(hy0 + hy, 0), 31);
        int ggz = min(max(hz0 + hz, 0), 31);
        int gv = (ggx << 10) + (ggy << 5) + ggz;
        float4 kk = *(const float4*)&g_qkv[gv * 384 + 128 + c4 * 4];
        int hh = c4 >> 3, d4 = c4 & 7;
        int col = hh * 32 + (((d4 ^ p) & 7) << 2);
        *(float4*)&buf[p * 128 + col] = kk;
    }

    ull q2[16];
    {
        const ull s2 = pack2(SCALE, SCALE);
        const ulonglong2* qp = (const ulonglong2*)&g_qkv[gv0 * 384 + hb];
        #pragma unroll
        for (int c = 0; c < 8; c++) {
            ulonglong2 t = qp[c];
            q2[2 * c] = fmul2(t.x, s2);
            q2[2 * c + 1] = fmul2(t.y, s2);
        }
    }
    __syncthreads();

    const int sx = min(max(gx - 1, 0), 29) - hx0;
    const int sy = min(max(gy - 1, 0), 29) - hy0;
    const int sz = min(max(gz - 1, 0), 29) - hz0;

    float sc[27];
    #pragma unroll
    for (int dx = 0; dx < 3; dx++)
    #pragma unroll
    for (int dy = 0; dy < 3; dy++)
    #pragma unroll
    for (int dz = 0; dz < 3; dz++) {
        int p = (sx + dx) * 36 + (sy + dy) * 6 + (sz + dz);
        int base = p * 128 + hb;
        int sw = p & 7;
        ull a0 = 0ull, a1 = 0ull;
        #pragma unroll
        for (int d4 = 0; d4 < 8; d4++) {
            ulonglong2 kk = *(const ulonglong2*)&buf[base + ((d4 ^ sw) << 2)];
            a0 = ffma2(q2[2 * d4], kk.x, a0);
            a1 = ffma2(q2[2 * d4 + 1], kk.y, a1);
        }
        float e0, e1, e2, e3;
        unpack2(a0, e0, e1); unpack2(a1, e2, e3);
        sc[dx * 9 + dy * 3 + dz] = (e0 + e1) + (e2 + e3);
    }

    float mx = sc[0];
    #pragma unroll
    for (int n = 1; n < 27; n++) mx = fmaxf(mx, sc[n]);
    float sum = 0.f;
    #pragma unroll
    for (int n = 0; n < 27; n++) { float e = __expf(sc[n] - mx); sc[n] = e; sum += e; }
    float inv = __fdividef(1.f, sum);

    // Phase V
    __syncthreads();
    for (int i = tid; i < 216 * 32; i += 256) {
        int p = i >> 5, c4 = i & 31;
        int hx = p / 36, r = p - hx * 36, hy = r / 6, hz = r - hy * 6;
        int ggx = min(max(hx0 + hx, 0), 31);
        int ggy = min(max(hy0 + hy, 0), 31);
        int ggz = min(max(hz0 + hz, 0), 31);
        int gv = (ggx << 10) + (ggy << 5) + ggz;
        float4 vv = *(const float4*)&g_qkv[gv * 384 + 256 + c4 * 4];
        int hh = c4 >> 3, d4 = c4 & 7;
        int col = hh * 32 + (((d4 ^ p) & 7) << 2);
        *(float4*)&buf[p * 128 + col] = vv;
    }
    __syncthreads();

    ull o2[16];
    #pragma unroll
    for (int i = 0; i < 16; i++) o2[i] = 0ull;

    #pragma unroll
    for (int dx = 0; dx < 3; dx++)
    #pragma unroll
    for (int dy = 0; dy < 3; dy++)
    #pragma unroll
    for (int dz = 0; dz < 3; dz++) {
        int p = (sx + dx) * 36 + (sy + dy) * 6 + (sz + dz);
        int base = p * 128 + hb;
        int sw = p & 7;
        ull w2 = pack2(sc[dx * 9 + dy * 3 + dz], sc[dx * 9 + dy * 3 + dz]);
        #pragma unroll
        for (int d4 = 0; d4 < 8; d4++) {
            ulonglong2 vv = *(const ulonglong2*)&buf[base + ((d4 ^ sw) << 2)];
            o2[2 * d4] = ffma2(w2, vv.x, o2[2 * d4]);
            o2[2 * d4 + 1] = ffma2(w2, vv.y, o2[2 * d4 + 1]);
        }
    }

    // transpose through smem -> float4 stores to g_attn[c][v]
    __syncthreads();                     // buf reads done; reuse as sbuf[128][64]
    #pragma unroll
    for (int c = 0; c < 16; c++) {
        float f0, f1;
        unpack2(o2[c], f0, f1);
        buf[(hb + 2 * c) * 64 + j] = f0 * inv;
        buf[(hb + 2 * c + 1) * 64 + j] = f1 * inv;
    }
    __syncthreads();
    for (int i = tid; i < 128 * 16; i += 256) {
        int c = i >> 4, r = i & 15;
        int vlx = r >> 2, vly = r & 3;
        float4 v4 = *(const float4*)&buf[c * 64 + vlx * 16 + vly * 4];
        *(float4*)&g_attn[c * NVOX + (((tx * 4 + vlx) << 10) + ((ty * 4 + vly) << 5) + tz * 4)] = v4;
    }
}

// ---------------------------------------------------------------------------
// Kernel 3: proj GEMM (mma.sync) + bias + residual.  CTA = 128 voxels.
// ---------------------------------------------------------------------------
__global__ void __launch_bounds__(256) proj_mma(
    const float* __restrict__ x, const float* __restrict__ pw,
    const float* __restrict__ pb, float* __restrict__ out)
{
    extern __shared__ char smem[];
    const int tid = threadIdx.x, lane = tid & 31, wid = tid >> 5;
    const int vb = blockIdx.x * 128;

    // ---- A conversion: g_attn[c][v] -> A tiles [v][k], registers only ----
    {
        const int v = tid >> 1, q = tid & 1;
        float r[64];
        const float* ap = g_attn + (q * 64) * NVOX + vb + v;
        #pragma unroll 8
        for (int i = 0; i < 64; i++) r[i] = ap[i * NVOX];
        #pragma unroll
        for (int j = 0; j < 8; j++) {
            uint4 hi, lo; split8(&r[8 * j], hi, lo);
            int chunk = q * 8 + j;
            *(uint4*)(smem + OFF_AH + v * (TSTRIDE * 2) + chunk * 16) = hi;
            *(uint4*)(smem + OFF_AL + v * (TSTRIDE * 2) + chunk * 16) = lo;
        }
    }

    // stage B: proj_w K-major native
    #pragma unroll
    for (int t = 0; t < 8; t++) {
        int task = tid + t * 256;
        int n = task >> 4, kc = task & 15;
        float vals[8];
        *(float4*)&vals[0] = *(const float4*)&pw[n * 128 + kc * 8];
        *(float4*)&vals[4] = *(const float4*)&pw[n * 128 + kc * 8 + 4];
        uint4 hi, lo; split8(vals, hi, lo);
        *(uint4*)(smem + OFF_BH + n * (TSTRIDE * 2) + kc * 16) = hi;
        *(uint4*)(smem + OFF_BL + n * (TSTRIDE * 2) + kc * 16) = lo;
    }
    __syncthreads();

    const int g = lane >> 2, t2 = lane & 3;
    const int m0 = (wid & 3) * 32, n0 = (wid >> 2) * 64;

    float acc[2][8][4];
    #pragma unroll
    for (int nt = 0; nt < 8; nt++) {
        float b0 = __ldg(&pb[n0 + nt * 8 + t2 * 2]);
        float b1 = __ldg(&pb[n0 + nt * 8 + t2 * 2 + 1]);
        acc[0][nt][0] = b0; acc[0][nt][1] = b1; acc[0][nt][2] = b0; acc[0][nt][3] = b1;
        acc[1][nt][0] = b0; acc[1][nt][1] = b1; acc[1][nt][2] = b0; acc[1][nt][3] = b1;
    }

    mma_mainloop(acc, smem, m0, n0, g, t2);

    // ---- transpose D through smem (reuse B region): ts[c][v], stride 132 ----
    __syncthreads();
    float* ts = (float*)(smem + OFF_BH);
    #pragma unroll
    for (int mt = 0; mt < 2; mt++) {
        int row = m0 + mt * 16 + g;
        #pragma unroll
        for (int nt = 0; nt < 8; nt++) {
            int col = n0 + nt * 8 + t2 * 2;
            ts[col * 132 + row]             = acc[mt][nt][0];
            ts[(col + 1) * 132 + row]       = acc[mt][nt][1];
            ts[col * 132 + row + 8]         = acc[mt][nt][2];
            ts[(col + 1) * 132 + row + 8]   = acc[mt][nt][3];
        }
    }
    __syncthreads();

    // final: residual + coalesced channel-major stores
    for (int i = tid; i < 128 * 32; i += 256) {
        int c = i >> 5, vq = i & 31;
        int off = c * NVOX + vb + vq * 4;
        float4 t = *(const float4*)&ts[c * 132 + vq * 4];
        float4 xr = *(const float4*)&x[off];
        *(float4*)&out[off] = make_float4(t.x + xr.x, t.y + xr.y, t.z + xr.z, t.w + xr.w);
    }
}

// ---------------------------------------------------------------------------
extern "C" void kernel_launch(void* const* d_in, const int* in_sizes, int n_in,
                              void* d_out, int out_size)
{
    const float* x   = (const float*)d_in[0];
    const float* gam = (const float*)d_in[1];
    const float* bet = (const float*)d_in[2];
    const float* qw  = (const float*)d_in[3];
    const float* qb  = (const float*)d_in[4];
    const float* pw  = (const float*)d_in[5];
    const float* pb  = (const float*)d_in[6];
    float* out = (float*)d_out;

    const int SMEM_ATTN = 216 * 128 * 4;   // 110592

    cudaFuncSetAttribute(lnqkv_mma,   cudaFuncAttributeMaxDynamicSharedMemorySize, SMEM_MMA);
    cudaFuncSetAttribute(attn_kernel, cudaFuncAttributeMaxDynamicSharedMemorySize, SMEM_ATTN);
    cudaFuncSetAttribute(proj_mma,    cudaFuncAttributeMaxDynamicSharedMemorySize, SMEM_MMA);

    lnqkv_mma<<<256, 256, SMEM_MMA>>>(x, gam, bet, qw, qb);
    attn_kernel<<<512, 256, SMEM_ATTN>>>();
    proj_mma<<<256, 256, SMEM_MMA>>>(x, pw, pb, out);
}

// round 5
// speedup vs baseline: 1.5859x; 1.3996x over previous
#include <cuda_runtime.h>
#include <cuda_fp16.h>
#include <cuda_bf16.h>
#include <cstdint>

#define NVOX 32768
#define SCALE 0.17677669529663689f   // 1/sqrt(32)

// Scratch (allocation-free: device globals)
__device__ __align__(16) float        g_q[NVOX * 128];     // [v][128] fp32
__device__ __align__(16) __half       g_kv[NVOX * 256];    // [v][ k:128 | v:128 ] fp16
__device__ __align__(16) float        g_attn[128 * NVOX];  // [c][v] fp32
__device__ __align__(16) __nv_bfloat16 g_wh[384 * 128];    // qkv_w hi (K-major rows)
__device__ __align__(16) __nv_bfloat16 g_wl[384 * 128];    // qkv_w lo
__device__ __align__(16) __nv_bfloat16 g_ph[128 * 128];    // proj_w hi
__device__ __align__(16) __nv_bfloat16 g_pl[128 * 128];    // proj_w lo

// ---------------------------------------------------------------------------
// PTX helpers
// ---------------------------------------------------------------------------
__device__ __forceinline__ uint32_t smem_u32(const void* p) {
    uint32_t a;
    asm("{ .reg .u64 t; cvta.to.shared.u64 t, %1; cvt.u32.u64 %0, t; }" : "=r"(a) : "l"(p));
    return a;
}
__device__ __forceinline__ void ldsm4(uint32_t* f, uint32_t addr) {
    asm volatile("ldmatrix.sync.aligned.m8n8.x4.shared.b16 {%0,%1,%2,%3}, [%4];"
        : "=r"(f[0]), "=r"(f[1]), "=r"(f[2]), "=r"(f[3]) : "r"(addr));
}
__device__ __forceinline__ void cpasync16(uint32_t dst, const void* src) {
    asm volatile("cp.async.cg.shared.global [%0], [%1], 16;" :: "r"(dst), "l"(src));
}
#define CP_COMMIT() asm volatile("cp.async.commit_group;" ::: "memory")
#define CP_WAIT(n)  asm volatile("cp.async.wait_group %0;" :: "n"(n) : "memory")

// warp mma: D(16x8,f32) += A(16x16 bf16,row) * B(16x8 bf16,col)
__device__ __forceinline__ void mma16816(float* d, const uint32_t* a, const uint32_t* b) {
    asm volatile(
        "mma.sync.aligned.m16n8k16.row.col.f32.bf16.bf16.f32 "
        "{%0,%1,%2,%3}, {%4,%5,%6,%7}, {%8,%9}, {%0,%1,%2,%3};"
        : "+f"(d[0]), "+f"(d[1]), "+f"(d[2]), "+f"(d[3])
        : "r"(a[0]), "r"(a[1]), "r"(a[2]), "r"(a[3]), "r"(b[0]), "r"(b[1]));
}

// split-convert 8 fp32 -> 8 bf16 hi + 8 bf16 lo, packed as uint4 each
__device__ __forceinline__ void split8(const float* v, uint4& hi, uint4& lo) {
    uint32_t h[4], l[4];
    #pragma unroll
    for (int i = 0; i < 4; i++) {
        __nv_bfloat16 h0 = __float2bfloat16_rn(v[2 * i]);
        __nv_bfloat16 h1 = __float2bfloat16_rn(v[2 * i + 1]);
        __nv_bfloat16 l0 = __float2bfloat16_rn(v[2 * i]     - __bfloat162float(h0));
        __nv_bfloat16 l1 = __float2bfloat16_rn(v[2 * i + 1] - __bfloat162float(h1));
        h[i] = (uint32_t)__bfloat16_as_ushort(h0) | ((uint32_t)__bfloat16_as_ushort(h1) << 16);
        l[i] = (uint32_t)__bfloat16_as_ushort(l0) | ((uint32_t)__bfloat16_as_ushort(l1) << 16);
    }
    hi = make_uint4(h[0], h[1], h[2], h[3]);
    lo = make_uint4(l[0], l[1], l[2], l[3]);
}

// tile geometry: bf16 [row][k], row stride 136 elems (272 B)
#define RSTRIDE 272
#define TILE_B  34816      // 128 * 272

// ---------------------------------------------------------------------------
// Kernel 0: pre-split weights to bf16 hi/lo
// ---------------------------------------------------------------------------
__global__ void prep_kernel(const float* __restrict__ qw, const float* __restrict__ pw) {
    int i = blockIdx.x * 256 + threadIdx.x;
    if (i < 384 * 128) {
        float w = qw[i];
        __nv_bfloat16 h = __float2bfloat16_rn(w);
        g_wh[i] = h;
        g_wl[i] = __float2bfloat16_rn(w - __bfloat162float(h));
    }
    if (i < 128 * 128) {
        float w = pw[i];
        __nv_bfloat16 h = __float2bfloat16_rn(w);
        g_ph[i] = h;
        g_pl[i] = __float2bfloat16_rn(w - __bfloat162float(h));
    }
}

// ---------------------------------------------------------------------------
// GEMM mainloop: 8 warps 4m x 2n, warp tile 32x64, 3-term bf16 split.
// aA: lane's A-hi ldmatrix address (A-lo at +TILE_B).
// aB: lane's B-hi ldmatrix address (B-lo at +TILE_B).
// ---------------------------------------------------------------------------
__device__ __forceinline__ void mma_loop(float acc[2][8][4], uint32_t aA, uint32_t aB)
{
    #pragma unroll
    for (int ks = 0; ks < 8; ks++) {
        uint32_t Ah[2][4], Al[2][4], Bh[4][4], Bl[4][4];
        ldsm4(Ah[0], aA + ks * 32);
        ldsm4(Ah[1], aA + 16 * RSTRIDE + ks * 32);
        ldsm4(Al[0], aA + TILE_B + ks * 32);
        ldsm4(Al[1], aA + TILE_B + 16 * RSTRIDE + ks * 32);
        #pragma unroll
        for (int np = 0; np < 4; np++) {
            ldsm4(Bh[np], aB + np * 16 * RSTRIDE + ks * 32);
            ldsm4(Bl[np], aB + TILE_B + np * 16 * RSTRIDE + ks * 32);
        }
        #pragma unroll
        for (int np = 0; np < 4; np++) {
            uint32_t b0h[2] = { Bh[np][0], Bh[np][2] };
            uint32_t b1h[2] = { Bh[np][1], Bh[np][3] };
            uint32_t b0l[2] = { Bl[np][0], Bl[np][2] };
            uint32_t b1l[2] = { Bl[np][1], Bl[np][3] };
            mma16816(acc[0][2*np],   Ah[0], b0h);
            mma16816(acc[1][2*np],   Ah[1], b0h);
            mma16816(acc[0][2*np+1], Ah[0], b1h);
            mma16816(acc[1][2*np+1], Ah[1], b1h);
            mma16816(acc[0][2*np],   Al[0], b0h);
            mma16816(acc[1][2*np],   Al[1], b0h);
            mma16816(acc[0][2*np+1], Al[0], b1h);
            mma16816(acc[1][2*np+1], Al[1], b1h);
            mma16816(acc[0][2*np],   Ah[0], b0l);
            mma16816(acc[1][2*np],   Ah[1], b0l);
            mma16816(acc[0][2*np+1], Ah[0], b1l);
            mma16816(acc[1][2*np+1], Ah[1], b1l);
        }
    }
}

// smem map (lnqkv): A_hi 0, A_lo 34816, Bbuf0 69632(+lo 104448), Bbuf1 139264(+lo 174080)
#define SM_LNQKV 208896
// smem map (proj):  A_hi 0, A_lo 34816, B 69632(+lo 104448); ts overlays B
#define SM_PROJ  139264

// ---------------------------------------------------------------------------
// Kernel 1: LN (registers) + QKV GEMM.  CTA = 128 voxels, 256 threads.
// Q -> g_q fp32; K,V -> g_kv fp16.
// ---------------------------------------------------------------------------
__global__ void __launch_bounds__(256) lnqkv_mma(
    const float* __restrict__ x, const float* __restrict__ gam,
    const float* __restrict__ bet, const float* __restrict__ qb)
{
    extern __shared__ char smem[];
    const int tid = threadIdx.x, lane = tid & 31, wid = tid >> 5;
    const int vb = blockIdx.x * 128;
    const uint32_t sb = smem_u32(smem);

    // prefetch B chunk 0 (group 0)
    #pragma unroll
    for (int t = 0; t < 8; t++) {
        int task = tid + t * 256;          // 2048 tasks: n(128) x c(16)
        int n = task >> 4, c = task & 15;
        cpasync16(sb + 69632  + n * RSTRIDE + c * 16, (const char*)g_wh + n * 256 + c * 16);
        cpasync16(sb + 104448 + n * RSTRIDE + c * 16, (const char*)g_wl + n * 256 + c * 16);
    }
    CP_COMMIT();

    // ---- LayerNorm in registers: 2 threads per voxel ----
    {
        const int v = tid >> 1, q = tid & 1;
        float r[64];
        const float* xp = x + (q * 64) * NVOX + vb + v;
        #pragma unroll 8
        for (int i = 0; i < 64; i++) r[i] = xp[i * NVOX];
        float s = 0.f, s2 = 0.f;
        #pragma unroll
        for (int i = 0; i < 64; i++) { s += r[i]; s2 += r[i] * r[i]; }
        s  += __shfl_xor_sync(0xffffffffu, s, 1);
        s2 += __shfl_xor_sync(0xffffffffu, s2, 1);
        float mu = s * (1.f / 128.f);
        float var = s2 * (1.f / 128.f) - mu * mu;
        float rs = rsqrtf(var + 1e-5f);
        #pragma unroll 8
        for (int i = 0; i < 64; i++) {
            int c = q * 64 + i;
            r[i] = (r[i] - mu) * rs * __ldg(&gam[c]) + __ldg(&bet[c]);
        }
        #pragma unroll
        for (int j = 0; j < 8; j++) {
            uint4 hi, lo; split8(&r[8 * j], hi, lo);
            int chunk = q * 8 + j;
            *(uint4*)(smem + v * RSTRIDE + chunk * 16)          = hi;
            *(uint4*)(smem + TILE_B + v * RSTRIDE + chunk * 16) = lo;
        }
    }
    __syncthreads();   // A tiles ready

    const int g = lane >> 2, t2 = lane & 3;
    const int m0 = (wid & 3) * 32, n0 = (wid >> 2) * 64;
    const uint32_t aA = sb + (m0 + (lane & 15)) * RSTRIDE + (lane >> 4) * 16;
    const uint32_t aBlane = (n0 + (lane & 15)) * RSTRIDE + (lane >> 4) * 16;

    #pragma unroll
    for (int nc = 0; nc < 3; nc++) {
        if (nc > 0) __syncthreads();       // all warps done reading buf[(nc+1)&1]
        if (nc < 2) {                      // prefetch chunk nc+1 into other buffer
            uint32_t boff = ((nc + 1) & 1) ? 139264u : 69632u;
            #pragma unroll
            for (int t = 0; t < 8; t++) {
                int task = tid + t * 256;
                int n = task >> 4, c = task & 15;
                cpasync16(sb + boff + n * RSTRIDE + c * 16,
                          (const char*)g_wh + ((nc + 1) * 128 + n) * 256 + c * 16);
                cpasync16(sb + boff + TILE_B + n * RSTRIDE + c * 16,
                          (const char*)g_wl + ((nc + 1) * 128 + n) * 256 + c * 16);
            }
            CP_COMMIT();
            CP_WAIT(1);
        } else {
            CP_WAIT(0);
        }
        __syncthreads();                   // current buffer visible to all

        float acc[2][8][4];
        #pragma unroll
        for (int nt = 0; nt < 8; nt++) {
            float b0 = __ldg(&qb[nc * 128 + n0 + nt * 8 + t2 * 2]);
            float b1 = __ldg(&qb[nc * 128 + n0 + nt * 8 + t2 * 2 + 1]);
            acc[0][nt][0] = b0; acc[0][nt][1] = b1; acc[0][nt][2] = b0; acc[0][nt][3] = b1;
            acc[1][nt][0] = b0; acc[1][nt][1] = b1; acc[1][nt][2] = b0; acc[1][nt][3] = b1;
        }

        mma_loop(acc, aA, sb + ((nc & 1) ? 139264u : 69632u) + aBlane);

        // epilogue
        #pragma unroll
        for (int mt = 0; mt < 2; mt++) {
            int row = vb + m0 + mt * 16 + g;
            #pragma unroll
            for (int nt = 0; nt < 8; nt++) {
                int col = n0 + nt * 8 + t2 * 2;
                if (nc == 0) {
                    *(float2*)&g_q[row * 128 + col]       = make_float2(acc[mt][nt][0], acc[mt][nt][1]);
                    *(float2*)&g_q[(row + 8) * 128 + col] = make_float2(acc[mt][nt][2], acc[mt][nt][3]);
                } else {
                    uint32_t* kv = (uint32_t*)g_kv;
                    int base = (nc == 1) ? 0 : 64;
                    __half2 h0 = __floats2half2_rn(acc[mt][nt][0], acc[mt][nt][1]);
                    __half2 h1 = __floats2half2_rn(acc[mt][nt][2], acc[mt][nt][3]);
                    kv[row * 128 + base + (col >> 1)]       = *(uint32_t*)&h0;
                    kv[(row + 8) * 128 + base + (col >> 1)] = *(uint32_t*)&h1;
                }
            }
        }
    }
}

// ---------------------------------------------------------------------------
// Kernel 2: 27-neighbor attention, fp16 K/V, single-phase halo, HFMA2.
// Block = 4x4x4 spatial tile x 4 heads, 256 threads, 2 blocks/SM.
// smem: K planes 216*256B + V planes 216*256B = 110592
// ---------------------------------------------------------------------------
__global__ void __launch_bounds__(256, 2) attn_kernel() {
    extern __shared__ char smem[];
    char* ksm = smem;
    char* vsm = smem + 55296;
    const int tid = threadIdx.x;
    const int b = blockIdx.x;
    const int tx = b >> 6, ty = (b >> 3) & 7, tz = b & 7;
    const int hx0 = tx * 4 - 1, hy0 = ty * 4 - 1, hz0 = tz * 4 - 1;

    const int j = tid & 63, h = tid >> 6;
    const int lx = j >> 4, ly = (j >> 2) & 3, lz = j & 3;
    const int gx = tx * 4 + lx, gy = ty * 4 + ly, gz = tz * 4 + lz;
    const int gv0 = (gx << 10) + (gy << 5) + gz;
    const int hb = h * 32;

    // halo load: 216 positions x 512B (K 256 + V 256), 16B chunks, swizzled
    for (int i = tid; i < 216 * 32; i += 256) {
        int p = i >> 5, c = i & 31;
        int hx = p / 36, r = p - hx * 36, hy = r / 6, hz = r - hy * 6;
        int ggx = min(max(hx0 + hx, 0), 31);
        int ggy = min(max(hy0 + hy, 0), 31);
        int ggz = min(max(hz0 + hz, 0), 31);
        int gv = (ggx << 10) + (ggy << 5) + ggz;
        uint4 t = *(const uint4*)((const char*)g_kv + gv * 512 + c * 16);
        char* base = (c < 16) ? ksm : vsm;
        int cc = c & 15;
        *(uint4*)(base + p * 256 + ((cc ^ (p & 15)) << 4)) = t;
    }

    // q -> half2, pre-scaled
    __half2 qh[16];
    {
        const float2* qp = (const float2*)&g_q[gv0 * 128 + hb];
        #pragma unroll
        for (int c = 0; c < 16; c++) {
            float2 t = qp[c];
            qh[c] = __floats2half2_rn(t.x * SCALE, t.y * SCALE);
        }
    }
    __syncthreads();

    const int sx = min(max(gx - 1, 0), 29) - hx0;
    const int sy = min(max(gy - 1, 0), 29) - hy0;
    const int sz = min(max(gz - 1, 0), 29) - hz0;

    const __half2 z2 = __float2half2_rn(0.f);
    float sc[27];
    #pragma unroll
    for (int dx = 0; dx < 3; dx++)
    #pragma unroll
    for (int dy = 0; dy < 3; dy++)
    #pragma unroll
    for (int dz = 0; dz < 3; dz++) {
        int p = (sx + dx) * 36 + (sy + dy) * 6 + (sz + dz);
        const char* kb = ksm + p * 256;
        int psw = p & 15;
        __half2 a0 = z2, a1 = z2, a2 = z2, a3 = z2;
        #pragma unroll
        for (int cc = 0; cc < 4; cc++) {
            uint4 t = *(const uint4*)(kb + (((h * 4 + cc) ^ psw) << 4));
            const __half2* kk = (const __half2*)&t;
            a0 = __hfma2(qh[cc * 4 + 0], kk[0], a0);
            a1 = __hfma2(qh[cc * 4 + 1], kk[1], a1);
            a2 = __hfma2(qh[cc * 4 + 2], kk[2], a2);
            a3 = __hfma2(qh[cc * 4 + 3], kk[3], a3);
        }
        __half2 as = __hadd2(__hadd2(a0, a1), __hadd2(a2, a3));
        float2 f = __half22float2(as);
        sc[dx * 9 + dy * 3 + dz] = f.x + f.y;
    }

    // softmax (fp32)
    float mx = sc[0];
    #pragma unroll
    for (int n = 1; n < 27; n++) mx = fmaxf(mx, sc[n]);
    float sum = 0.f;
    #pragma unroll
    for (int n = 0; n < 27; n++) { float e = __expf(sc[n] - mx); sc[n] = e; sum += e; }
    float inv = __fdividef(1.f, sum);

    // weighted V sum (HFMA2)
    __half2 out[16];
    #pragma unroll
    for (int i = 0; i < 16; i++) out[i] = z2;

    #pragma unroll
    for (int dx = 0; dx < 3; dx++)
    #pragma unroll
    for (int dy = 0; dy < 3; dy++)
    #pragma unroll
    for (int dz = 0; dz < 3; dz++) {
        int p = (sx + dx) * 36 + (sy + dy) * 6 + (sz + dz);
        const char* vbp = vsm + p * 256;
        int psw = p & 15;
        __half2 wh = __float2half2_rn(sc[dx * 9 + dy * 3 + dz]);
        #pragma unroll
        for (int cc = 0; cc < 4; cc++) {
            uint4 t = *(const uint4*)(vbp + (((h * 4 + cc) ^ psw) << 4));
            const __half2* vv = (const __half2*)&t;
            out[cc * 4 + 0] = __hfma2(wh, vv[0], out[cc * 4 + 0]);
            out[cc * 4 + 1] = __hfma2(wh, vv[1], out[cc * 4 + 1]);
            out[cc * 4 + 2] = __hfma2(wh, vv[2], out[cc * 4 + 2]);
            out[cc * 4 + 3] = __hfma2(wh, vv[3], out[cc * 4 + 3]);
        }
    }

    // transpose through smem -> float4 stores to g_attn[c][v]
    __syncthreads();
    float* buf = (float*)ksm;            // 128*64 floats = 32768 B
    #pragma unroll
    for (int c = 0; c < 16; c++) {
        float2 f = __half22float2(out[c]);
        buf[(hb + 2 * c) * 64 + j]     = f.x * inv;
        buf[(hb + 2 * c + 1) * 64 + j] = f.y * inv;
    }
    __syncthreads();
    for (int i = tid; i < 128 * 16; i += 256) {
        int c = i >> 4, r = i & 15;
        int vlx = r >> 2, vly = r & 3;
        float4 v4 = *(const float4*)&buf[c * 64 + vlx * 16 + vly * 4];
        *(float4*)&g_attn[c * NVOX + (((tx * 4 + vlx) << 10) + ((ty * 4 + vly) << 5) + tz * 4)] = v4;
    }
}

// ---------------------------------------------------------------------------
// Kernel 3: proj GEMM + bias + residual.  CTA = 128 voxels, 256 threads.
// ---------------------------------------------------------------------------
__global__ void __launch_bounds__(256) proj_mma(
    const float* __restrict__ x, const float* __restrict__ pb, float* __restrict__ out)
{
    extern __shared__ char smem[];
    const int tid = threadIdx.x, lane = tid & 31, wid = tid >> 5;
    const int vb = blockIdx.x * 128;
    const uint32_t sb = smem_u32(smem);

    // prefetch B (hi+lo) via cp.async
    #pragma unroll
    for (int t = 0; t < 8; t++) {
        int task = tid + t * 256;
        int n = task >> 4, c = task & 15;
        cpasync16(sb + 69632  + n * RSTRIDE + c * 16, (const char*)g_ph + n * 256 + c * 16);
        cpasync16(sb + 104448 + n * RSTRIDE + c * 16, (const char*)g_pl + n * 256 + c * 16);
    }
    CP_COMMIT();

    // A conversion: g_attn[c][v] -> A hi/lo tiles
    {
        const int v = tid >> 1, q = tid & 1;
        float r[64];
        const float* ap = g_attn + (q * 64) * NVOX + vb + v;
        #pragma unroll 8
        for (int i = 0; i < 64; i++) r[i] = ap[i * NVOX];
        #pragma unroll
        for (int jj = 0; jj < 8; jj++) {
            uint4 hi, lo; split8(&r[8 * jj], hi, lo);
            int chunk = q * 8 + jj;
            *(uint4*)(smem + v * RSTRIDE + chunk * 16)          = hi;
            *(uint4*)(smem + TILE_B + v * RSTRIDE + chunk * 16) = lo;
        }
    }
    CP_WAIT(0);
    __syncthreads();

    const int g = lane >> 2, t2 = lane & 3;
    const int m0 = (wid & 3) * 32, n0 = (wid >> 2) * 64;
    const uint32_t aA = sb + (m0 + (lane & 15)) * RSTRIDE + (lane >> 4) * 16;
    const uint32_t aB = sb + 69632 + (n0 + (lane & 15)) * RSTRIDE + (lane >> 4) * 16;

    float acc[2][8][4];
    #pragma unroll
    for (int nt = 0; nt < 8; nt++) {
        float b0 = __ldg(&pb[n0 + nt * 8 + t2 * 2]);
        float b1 = __ldg(&pb[n0 + nt * 8 + t2 * 2 + 1]);
        acc[0][nt][0] = b0; acc[0][nt][1] = b1; acc[0][nt][2] = b0; acc[0][nt][3] = b1;
        acc[1][nt][0] = b0; acc[1][nt][1] = b1; acc[1][nt][2] = b0; acc[1][nt][3] = b1;
    }

    mma_loop(acc, aA, aB);

    // transpose D through smem (B region dead): ts[c][v], stride 132
    __syncthreads();
    float* ts = (float*)(smem + 69632);
    #pragma unroll
    for (int mt = 0; mt < 2; mt++) {
        int row = m0 + mt * 16 + g;
        #pragma unroll
        for (int nt = 0; nt < 8; nt++) {
            int col = n0 + nt * 8 + t2 * 2;
            ts[col * 132 + row]           = acc[mt][nt][0];
            ts[(col + 1) * 132 + row]     = acc[mt][nt][1];
            ts[col * 132 + row + 8]       = acc[mt][nt][2];
            ts[(col + 1) * 132 + row + 8] = acc[mt][nt][3];
        }
    }
    __syncthreads();

    // residual + coalesced channel-major stores
    for (int i = tid; i < 128 * 32; i += 256) {
        int c = i >> 5, vq = i & 31;
        int off = c * NVOX + vb + vq * 4;
        float4 t = *(const float4*)&ts[c * 132 + vq * 4];
        float4 xr = *(const float4*)&x[off];
        *(float4*)&out[off] = make_float4(t.x + xr.x, t.y + xr.y, t.z + xr.z, t.w + xr.w);
    }
}

// ---------------------------------------------------------------------------
extern "C" void kernel_launch(void* const* d_in, const int* in_sizes, int n_in,
                              void* d_out, int out_size)
{
    const float* x   = (const float*)d_in[0];
    const float* gam = (const float*)d_in[1];
    const float* bet = (const float*)d_in[2];
    const float* qw  = (const float*)d_in[3];
    const float* qb  = (const float*)d_in[4];
    const float* pw  = (const float*)d_in[5];
    const float* pb  = (const float*)d_in[6];
    float* out = (float*)d_out;

    const int SMEM_ATTN = 110592;

    cudaFuncSetAttribute(lnqkv_mma,   cudaFuncAttributeMaxDynamicSharedMemorySize, SM_LNQKV);
    cudaFuncSetAttribute(attn_kernel, cudaFuncAttributeMaxDynamicSharedMemorySize, SMEM_ATTN);
    cudaFuncSetAttribute(proj_mma,    cudaFuncAttributeMaxDynamicSharedMemorySize, SM_PROJ);

    prep_kernel<<<192, 256>>>(qw, pw);
    lnqkv_mma<<<256, 256, SM_LNQKV>>>(x, gam, bet, qb);
    attn_kernel<<<512, 256, SMEM_ATTN>>>();
    proj_mma<<<256, 256, SM_PROJ>>>(x, pb, out);
}